// round 1
// baseline (speedup 1.0000x reference)
#include <cuda_runtime.h>
#include <math.h>

#define DIMC 384
#define B_   8
#define HH   56
#define WW   56
#define T1   3136
#define H2   28
#define W2   28
#define T2   784
#define NHEADS 6
#define HD   64
#define EPSBN 1e-5f
#define ATT_SCALE 0.05103103630798288f   /* 384^-0.5 (full dim, per reference) */

// ---------------- scratch (static device allocations are the sanctioned path) ----
__device__ float g_qf[B_ * T1 * DIMC];   // dwconv+bn q features
__device__ float g_kf[B_ * T2 * DIMC];
__device__ float g_vf[B_ * T2 * DIMC];
__device__ float g_qp[B_ * T1 * DIMC];   // projected q
__device__ float g_kp[B_ * T2 * DIMC];
__device__ float g_vp[B_ * T2 * DIMC];
__device__ float g_ob[B_ * T1 * DIMC];   // attention output (pre final linear)

// ---------------- depthwise conv 3x3 stride 1 + BN ------------------------------
__global__ __launch_bounds__(DIMC) void dwconv_s1(
    const float* __restrict__ x, const float* __restrict__ cw,
    const float* __restrict__ gs, const float* __restrict__ gb,
    const float* __restrict__ gm, const float* __restrict__ gv,
    float* __restrict__ out)
{
    int bt = blockIdx.x;            // b*T1 + t
    int c  = threadIdx.x;
    int b  = bt / T1, t = bt % T1;
    int y  = t / WW,  xw = t % WW;
    const float* xb = x + (size_t)b * T1 * DIMC + c;

    float w0 = cw[c*9+0], w1 = cw[c*9+1], w2 = cw[c*9+2];
    float w3 = cw[c*9+3], w4 = cw[c*9+4], w5 = cw[c*9+5];
    float w6 = cw[c*9+6], w7 = cw[c*9+7], w8 = cw[c*9+8];
    const float* wrow[3] = {nullptr, nullptr, nullptr};
    float acc = 0.f;
    #pragma unroll
    for (int ky = 0; ky < 3; ky++) {
        int yy = y + ky - 1;
        if (yy < 0 || yy >= HH) continue;
        #pragma unroll
        for (int kx = 0; kx < 3; kx++) {
            int xx = xw + kx - 1;
            if (xx < 0 || xx >= WW) continue;
            float xv = xb[(size_t)(yy * WW + xx) * DIMC];
            float w;
            int idx = ky * 3 + kx;
            switch (idx) {
                case 0: w = w0; break; case 1: w = w1; break; case 2: w = w2; break;
                case 3: w = w3; break; case 4: w = w4; break; case 5: w = w5; break;
                case 6: w = w6; break; case 7: w = w7; break; default: w = w8; break;
            }
            acc += xv * w;
        }
    }
    (void)wrow;
    float inv = rsqrtf(gv[c] + EPSBN);
    float sc  = gs[c] * inv;
    out[(size_t)bt * DIMC + c] = acc * sc + (gb[c] - gm[c] * sc);
}

// ---------------- depthwise conv 3x3 stride 2 + BN (k and v fused) --------------
__global__ __launch_bounds__(DIMC) void dwconv_s2(
    const float* __restrict__ x,
    const float* __restrict__ cwk, const float* __restrict__ ksc, const float* __restrict__ kbi,
    const float* __restrict__ kmu, const float* __restrict__ kva,
    const float* __restrict__ cwv, const float* __restrict__ vsc, const float* __restrict__ vbi,
    const float* __restrict__ vmu, const float* __restrict__ vva,
    float* __restrict__ outk, float* __restrict__ outv)
{
    int bt = blockIdx.x;            // b*T2 + t
    int c  = threadIdx.x;
    int b  = bt / T2, t = bt % T2;
    int oy = t / W2,  ox = t % W2;
    const float* xb = x + (size_t)b * T1 * DIMC + c;

    float ak = 0.f, av = 0.f;
    #pragma unroll
    for (int ky = 0; ky < 3; ky++) {
        int yy = 2 * oy + ky - 1;
        if (yy < 0 || yy >= HH) continue;
        #pragma unroll
        for (int kx = 0; kx < 3; kx++) {
            int xx = 2 * ox + kx - 1;
            if (xx < 0 || xx >= WW) continue;
            float xv = xb[(size_t)(yy * WW + xx) * DIMC];
            ak += xv * cwk[c*9 + ky*3 + kx];
            av += xv * cwv[c*9 + ky*3 + kx];
        }
    }
    float invk = rsqrtf(kva[c] + EPSBN);
    float sck  = ksc[c] * invk;
    outk[(size_t)bt * DIMC + c] = ak * sck + (kbi[c] - kmu[c] * sck);
    float invv = rsqrtf(vva[c] + EPSBN);
    float scv  = vsc[c] * invv;
    outv[(size_t)bt * DIMC + c] = av * scv + (vbi[c] - vmu[c] * scv);
}

// ---------------- tiled GEMM: C[M,384] = A[M,384] @ W[384,384]^T (+bias) --------
// BM=BN=64, BK=16, 256 threads, 4x4 micro-tile. M, N, K all divide evenly.
__global__ __launch_bounds__(256) void gemm_nt(
    const float* __restrict__ A, const float* __restrict__ W,
    const float* __restrict__ bias, float* __restrict__ C, int hasBias)
{
    __shared__ float As[16][68];
    __shared__ float Ws[16][68];

    int row0 = blockIdx.y * 64;
    int col0 = blockIdx.x * 64;
    int tid  = threadIdx.x;
    int tx   = tid & 15, ty = tid >> 4;

    float acc[4][4] = {};

    int lm = tid >> 2;              // 0..63
    int kq = (tid & 3) * 4;         // 0,4,8,12
    const float* Aptr = A + (size_t)(row0 + lm) * DIMC + kq;
    const float* Wptr = W + (size_t)(col0 + lm) * DIMC + kq;

    for (int k0 = 0; k0 < DIMC; k0 += 16) {
        float4 a = *(const float4*)(Aptr + k0);
        float4 w = *(const float4*)(Wptr + k0);
        As[kq+0][lm] = a.x; As[kq+1][lm] = a.y; As[kq+2][lm] = a.z; As[kq+3][lm] = a.w;
        Ws[kq+0][lm] = w.x; Ws[kq+1][lm] = w.y; Ws[kq+2][lm] = w.z; Ws[kq+3][lm] = w.w;
        __syncthreads();
        #pragma unroll
        for (int k = 0; k < 16; k++) {
            float4 av = *(const float4*)&As[k][ty * 4];
            float4 wv = *(const float4*)&Ws[k][tx * 4];
            acc[0][0] += av.x * wv.x; acc[0][1] += av.x * wv.y; acc[0][2] += av.x * wv.z; acc[0][3] += av.x * wv.w;
            acc[1][0] += av.y * wv.x; acc[1][1] += av.y * wv.y; acc[1][2] += av.y * wv.z; acc[1][3] += av.y * wv.w;
            acc[2][0] += av.z * wv.x; acc[2][1] += av.z * wv.y; acc[2][2] += av.z * wv.z; acc[2][3] += av.z * wv.w;
            acc[3][0] += av.w * wv.x; acc[3][1] += av.w * wv.y; acc[3][2] += av.w * wv.z; acc[3][3] += av.w * wv.w;
        }
        __syncthreads();
    }

    float4 bvec = make_float4(0.f, 0.f, 0.f, 0.f);
    if (hasBias) bvec = *(const float4*)&bias[col0 + tx * 4];
    #pragma unroll
    for (int i = 0; i < 4; i++) {
        int r = row0 + ty * 4 + i;
        float4 o;
        o.x = acc[i][0] + bvec.x;
        o.y = acc[i][1] + bvec.y;
        o.z = acc[i][2] + bvec.z;
        o.w = acc[i][3] + bvec.w;
        *(float4*)&C[(size_t)r * DIMC + col0 + tx * 4] = o;
    }
}

// ---------------- fused flash-style attention -----------------------------------
// Per block: one (batch, head, 32-query tile). Keys streamed in 64-wide tiles with
// online softmax. Shared KV buffer reused for K (as [d][n]) then V (as [n][dd]).
__global__ __launch_bounds__(256) void attn_kernel()
{
    __shared__ float Qs[64 * 32];        // Qs[d][m]
    __shared__ float KV[64 * 64];        // K phase: [d][n]; V phase: [n][dd]
    __shared__ float Ss[64 * 36];        // scores/probs [n][m], pad 36 (conflict-free)
    __shared__ float row_m[32], row_l[32], row_c[32];

    const int tid = threadIdx.x;
    const int q0  = blockIdx.x * 32;
    const int h   = blockIdx.y;
    const int b   = blockIdx.z;

    const float* qp = g_qp + (size_t)b * T1 * DIMC + h * HD;
    const float* kp = g_kp + (size_t)b * T2 * DIMC + h * HD;
    const float* vp = g_vp + (size_t)b * T2 * DIMC + h * HD;

    // load Q tile transposed: Qs[d][m]
    {
        int m  = tid >> 3;
        int d0 = (tid & 7) * 8;
        const float4* src = (const float4*)(qp + (size_t)(q0 + m) * DIMC + d0);
        float4 a = src[0], c = src[1];
        Qs[(d0+0)*32+m] = a.x; Qs[(d0+1)*32+m] = a.y; Qs[(d0+2)*32+m] = a.z; Qs[(d0+3)*32+m] = a.w;
        Qs[(d0+4)*32+m] = c.x; Qs[(d0+5)*32+m] = c.y; Qs[(d0+6)*32+m] = c.z; Qs[(d0+7)*32+m] = c.w;
    }
    if (tid < 32) { row_m[tid] = -INFINITY; row_l[tid] = 0.f; }

    const int n2 = tid & 31;             // key/dd pair index (2 cols each)
    const int mg = tid >> 5;             // row group (4 rows each)
    float acc_o[4][2] = {};

    for (int kk0 = 0; kk0 < T2; kk0 += 64) {
        __syncthreads();                 // protect KV/Q from previous-tile readers
        // ---- load K tile transposed: KV[d][n] ----
        {
            int nl = tid >> 2;
            int d0 = (tid & 3) * 16;
            int key = kk0 + nl;
            if (key < T2) {
                const float* src = kp + (size_t)key * DIMC + d0;
                #pragma unroll
                for (int q4 = 0; q4 < 4; q4++) {
                    float4 kvv = *(const float4*)(src + q4 * 4);
                    KV[(d0+q4*4+0)*64+nl] = kvv.x; KV[(d0+q4*4+1)*64+nl] = kvv.y;
                    KV[(d0+q4*4+2)*64+nl] = kvv.z; KV[(d0+q4*4+3)*64+nl] = kvv.w;
                }
            } else {
                #pragma unroll
                for (int dq = 0; dq < 16; dq++) KV[(d0+dq)*64+nl] = 0.f;
            }
        }
        __syncthreads();
        // ---- scores: S[m][n] = q . k ----
        float sc[4][2] = {};
        #pragma unroll 4
        for (int d = 0; d < 64; d++) {
            float4 qv  = *(const float4*)&Qs[d * 32 + mg * 4];   // broadcast
            float2 kv2 = *(const float2*)&KV[d * 64 + n2 * 2];
            sc[0][0] += qv.x * kv2.x; sc[0][1] += qv.x * kv2.y;
            sc[1][0] += qv.y * kv2.x; sc[1][1] += qv.y * kv2.y;
            sc[2][0] += qv.z * kv2.x; sc[2][1] += qv.z * kv2.y;
            sc[3][0] += qv.w * kv2.x; sc[3][1] += qv.w * kv2.y;
        }
        #pragma unroll
        for (int j = 0; j < 2; j++) {
            int n = n2 * 2 + j;
            bool valid = (kk0 + n) < T2;
            #pragma unroll
            for (int i = 0; i < 4; i++)
                Ss[n * 36 + mg * 4 + i] = valid ? sc[i][j] * ATT_SCALE : -1e30f;
        }
        __syncthreads();
        // ---- load V tile (overwrites K region): KV[n][dd] ----
        {
            int nl = tid >> 2;
            int d0 = (tid & 3) * 16;
            int key = kk0 + nl;
            float4* dst = (float4*)&KV[nl * 64 + d0];
            if (key < T2) {
                const float* src = vp + (size_t)key * DIMC + d0;
                #pragma unroll
                for (int q4 = 0; q4 < 4; q4++) dst[q4] = *(const float4*)(src + q4 * 4);
            } else {
                float4 z = make_float4(0.f, 0.f, 0.f, 0.f);
                #pragma unroll
                for (int q4 = 0; q4 < 4; q4++) dst[q4] = z;
            }
        }
        // ---- online softmax over this tile's 64 columns, 8 threads per row ----
        {
            int r = tid >> 3, sub = tid & 7;
            float lm = -INFINITY;
            #pragma unroll
            for (int jj = 0; jj < 8; jj++) lm = fmaxf(lm, Ss[(sub + jj * 8) * 36 + r]);
            lm = fmaxf(lm, __shfl_xor_sync(0xffffffffu, lm, 1));
            lm = fmaxf(lm, __shfl_xor_sync(0xffffffffu, lm, 2));
            lm = fmaxf(lm, __shfl_xor_sync(0xffffffffu, lm, 4));
            float om = row_m[r];
            float nm = fmaxf(om, lm);
            float ls = 0.f;
            #pragma unroll
            for (int jj = 0; jj < 8; jj++) {
                int n = sub + jj * 8;
                float e = __expf(Ss[n * 36 + r] - nm);
                Ss[n * 36 + r] = e;
                ls += e;
            }
            ls += __shfl_xor_sync(0xffffffffu, ls, 1);
            ls += __shfl_xor_sync(0xffffffffu, ls, 2);
            ls += __shfl_xor_sync(0xffffffffu, ls, 4);
            if (sub == 0) {
                float cf = __expf(om - nm);
                row_c[r] = cf;
                row_m[r] = nm;
                row_l[r] = row_l[r] * cf + ls;
            }
        }
        __syncthreads();
        // ---- rescale + accumulate O += P @ V ----
        {
            float cf0 = row_c[mg*4+0], cf1 = row_c[mg*4+1];
            float cf2 = row_c[mg*4+2], cf3 = row_c[mg*4+3];
            acc_o[0][0] *= cf0; acc_o[0][1] *= cf0;
            acc_o[1][0] *= cf1; acc_o[1][1] *= cf1;
            acc_o[2][0] *= cf2; acc_o[2][1] *= cf2;
            acc_o[3][0] *= cf3; acc_o[3][1] *= cf3;
            #pragma unroll 4
            for (int n = 0; n < 64; n++) {
                float4 p  = *(const float4*)&Ss[n * 36 + mg * 4];  // broadcast
                float2 vv = *(const float2*)&KV[n * 64 + n2 * 2];
                acc_o[0][0] += p.x * vv.x; acc_o[0][1] += p.x * vv.y;
                acc_o[1][0] += p.y * vv.x; acc_o[1][1] += p.y * vv.y;
                acc_o[2][0] += p.z * vv.x; acc_o[2][1] += p.z * vv.y;
                acc_o[3][0] += p.w * vv.x; acc_o[3][1] += p.w * vv.y;
            }
        }
    }
    __syncthreads();
    // ---- finalize: divide by l, write [B,T,C] with C = h*64 + dd ----
    float* ob = g_ob + ((size_t)b * T1 + q0) * DIMC + h * HD;
    #pragma unroll
    for (int i = 0; i < 4; i++) {
        int m = mg * 4 + i;
        float inv_l = 1.0f / row_l[m];
        float2 o2 = make_float2(acc_o[i][0] * inv_l, acc_o[i][1] * inv_l);
        *(float2*)&ob[(size_t)m * DIMC + n2 * 2] = o2;
    }
}

// ---------------- launch ---------------------------------------------------------
extern "C" void kernel_launch(void* const* d_in, const int* in_sizes, int n_in,
                              void* d_out, int out_size)
{
    (void)in_sizes; (void)n_in; (void)out_size;
    const float* x      = (const float*)d_in[0];
    // d_in[1], d_in[2] = h, w (known constants 56)
    const float* conv_q = (const float*)d_in[3];
    const float* bnq_s  = (const float*)d_in[4];
    const float* bnq_b  = (const float*)d_in[5];
    const float* bnq_m  = (const float*)d_in[6];
    const float* bnq_v  = (const float*)d_in[7];
    const float* conv_k = (const float*)d_in[8];
    const float* bnk_s  = (const float*)d_in[9];
    const float* bnk_b  = (const float*)d_in[10];
    const float* bnk_m  = (const float*)d_in[11];
    const float* bnk_v  = (const float*)d_in[12];
    const float* conv_v = (const float*)d_in[13];
    const float* bnv_s  = (const float*)d_in[14];
    const float* bnv_b  = (const float*)d_in[15];
    const float* bnv_m  = (const float*)d_in[16];
    const float* bnv_v  = (const float*)d_in[17];
    const float* wq     = (const float*)d_in[18];
    const float* wk     = (const float*)d_in[19];
    const float* wv     = (const float*)d_in[20];
    const float* w_last = (const float*)d_in[21];
    const float* b_last = (const float*)d_in[22];
    float* out = (float*)d_out;

    float *qf, *kf, *vf, *qp, *kp, *vp, *ob;
    cudaGetSymbolAddress((void**)&qf, g_qf);
    cudaGetSymbolAddress((void**)&kf, g_kf);
    cudaGetSymbolAddress((void**)&vf, g_vf);
    cudaGetSymbolAddress((void**)&qp, g_qp);
    cudaGetSymbolAddress((void**)&kp, g_kp);
    cudaGetSymbolAddress((void**)&vp, g_vp);
    cudaGetSymbolAddress((void**)&ob, g_ob);

    dwconv_s1<<<B_ * T1, DIMC>>>(x, conv_q, bnq_s, bnq_b, bnq_m, bnq_v, qf);
    dwconv_s2<<<B_ * T2, DIMC>>>(x, conv_k, bnk_s, bnk_b, bnk_m, bnk_v,
                                    conv_v, bnv_s, bnv_b, bnv_m, bnv_v, kf, vf);

    dim3 gbig(DIMC / 64, (B_ * T1) / 64);   // (6, 392)
    dim3 gsml(DIMC / 64, (B_ * T2) / 64);   // (6, 98)
    gemm_nt<<<gbig, 256>>>(qf, wq, nullptr, qp, 0);
    gemm_nt<<<gsml, 256>>>(kf, wk, nullptr, kp, 0);
    gemm_nt<<<gsml, 256>>>(vf, wv, nullptr, vp, 0);

    dim3 gattn(T1 / 32, NHEADS, B_);        // (98, 6, 8)
    attn_kernel<<<gattn, 256>>>();

    gemm_nt<<<gbig, 256>>>(ob, w_last, b_last, out, 1);
}

// round 2
// speedup vs baseline: 2.9271x; 2.9271x over previous
#include <cuda_runtime.h>
#include <math.h>
#include <stdint.h>

#define DIMC 384
#define B_   8
#define HH   56
#define WW   56
#define T1   3136
#define H2   28
#define W2   28
#define T2   784
#define NHEADS 6
#define HD   64
#define EPSBN 1e-5f
#define ATT_SCALE 0.05103103630798288f   /* 384^-0.5 (full dim, per reference) */

// ---------------- scratch ---------------------------------------------------
__device__ float g_qf[B_ * T1 * DIMC];
__device__ float g_kf[B_ * T2 * DIMC];
__device__ float g_vf[B_ * T2 * DIMC];
__device__ float g_qp[B_ * T1 * DIMC];
__device__ float g_kp[B_ * T2 * DIMC];
__device__ float g_vp[B_ * T2 * DIMC];
__device__ float g_ob[B_ * T1 * DIMC];

// ---------------- helpers ---------------------------------------------------
__device__ __forceinline__ float tf32r(float x) {
    uint32_t u;
    asm("cvt.rna.tf32.f32 %0, %1;" : "=r"(u) : "f"(x));
    return __uint_as_float(u);
}

// D += A(16x8) * B(8x8), tf32 inputs, fp32 accum.
__device__ __forceinline__ void mma8(float* d, const uint32_t* a, uint32_t b0, uint32_t b1) {
    asm volatile(
        "mma.sync.aligned.m16n8k8.row.col.f32.tf32.tf32.f32 "
        "{%0,%1,%2,%3}, {%4,%5,%6,%7}, {%8,%9}, {%0,%1,%2,%3};\n"
        : "+f"(d[0]), "+f"(d[1]), "+f"(d[2]), "+f"(d[3])
        : "r"(a[0]), "r"(a[1]), "r"(a[2]), "r"(a[3]), "r"(b0), "r"(b1));
}

// ---------------- depthwise conv 3x3 stride 1 + BN ---------------------------
__global__ __launch_bounds__(DIMC) void dwconv_s1(
    const float* __restrict__ x, const float* __restrict__ cw,
    const float* __restrict__ gs, const float* __restrict__ gb,
    const float* __restrict__ gm, const float* __restrict__ gv,
    float* __restrict__ out)
{
    int bt = blockIdx.x;
    int c  = threadIdx.x;
    int b  = bt / T1, t = bt % T1;
    int y  = t / WW,  xw = t % WW;
    const float* xb = x + (size_t)b * T1 * DIMC + c;

    float acc = 0.f;
    #pragma unroll
    for (int ky = 0; ky < 3; ky++) {
        int yy = y + ky - 1;
        if (yy < 0 || yy >= HH) continue;
        #pragma unroll
        for (int kx = 0; kx < 3; kx++) {
            int xx = xw + kx - 1;
            if (xx < 0 || xx >= WW) continue;
            acc += xb[(size_t)(yy * WW + xx) * DIMC] * cw[c*9 + ky*3 + kx];
        }
    }
    float inv = rsqrtf(gv[c] + EPSBN);
    float sc  = gs[c] * inv;
    out[(size_t)bt * DIMC + c] = acc * sc + (gb[c] - gm[c] * sc);
}

// ---------------- depthwise conv 3x3 stride 2 + BN (k and v fused) -----------
__global__ __launch_bounds__(DIMC) void dwconv_s2(
    const float* __restrict__ x,
    const float* __restrict__ cwk, const float* __restrict__ ksc, const float* __restrict__ kbi,
    const float* __restrict__ kmu, const float* __restrict__ kva,
    const float* __restrict__ cwv, const float* __restrict__ vsc, const float* __restrict__ vbi,
    const float* __restrict__ vmu, const float* __restrict__ vva,
    float* __restrict__ outk, float* __restrict__ outv)
{
    int bt = blockIdx.x;
    int c  = threadIdx.x;
    int b  = bt / T2, t = bt % T2;
    int oy = t / W2,  ox = t % W2;
    const float* xb = x + (size_t)b * T1 * DIMC + c;

    float ak = 0.f, av = 0.f;
    #pragma unroll
    for (int ky = 0; ky < 3; ky++) {
        int yy = 2 * oy + ky - 1;
        if (yy < 0 || yy >= HH) continue;
        #pragma unroll
        for (int kx = 0; kx < 3; kx++) {
            int xx = 2 * ox + kx - 1;
            if (xx < 0 || xx >= WW) continue;
            float xv = xb[(size_t)(yy * WW + xx) * DIMC];
            ak += xv * cwk[c*9 + ky*3 + kx];
            av += xv * cwv[c*9 + ky*3 + kx];
        }
    }
    float invk = rsqrtf(kva[c] + EPSBN);
    float sck  = ksc[c] * invk;
    outk[(size_t)bt * DIMC + c] = ak * sck + (kbi[c] - kmu[c] * sck);
    float invv = rsqrtf(vva[c] + EPSBN);
    float scv  = vsc[c] * invv;
    outv[(size_t)bt * DIMC + c] = av * scv + (vbi[c] - vmu[c] * scv);
}

// ---------------- tf32 tensor-core GEMM: C = A[M,384] @ W[384,384]^T (+bias) --
// 64x64 tile per block, 128 threads (4 warps), each warp 16 rows x 64 cols.
__global__ __launch_bounds__(128) void gemm_tf32(
    const float* __restrict__ A, const float* __restrict__ W,
    const float* __restrict__ bias, float* __restrict__ C, int hasBias)
{
    __shared__ float As[64 * 20];   // [m][k] stride 20 (conflict-free frags)
    __shared__ float Ws[64 * 20];   // [n][k] stride 20

    const int tid = threadIdx.x;
    const int w = tid >> 5, lane = tid & 31;
    const int g = lane >> 2, t = lane & 3;
    const int row0 = blockIdx.y * 64, col0 = blockIdx.x * 64;

    float acc[8][4] = {};

    for (int k0 = 0; k0 < DIMC; k0 += 16) {
        __syncthreads();
        #pragma unroll
        for (int p = 0; p < 2; p++) {
            int i = tid + p * 128;          // 0..255
            int r = i >> 2, c4 = (i & 3) << 2;
            float4 a = *(const float4*)(A + (size_t)(row0 + r) * DIMC + k0 + c4);
            *(float4*)&As[r * 20 + c4] =
                make_float4(tf32r(a.x), tf32r(a.y), tf32r(a.z), tf32r(a.w));
            float4 wv = *(const float4*)(W + (size_t)(col0 + r) * DIMC + k0 + c4);
            *(float4*)&Ws[r * 20 + c4] =
                make_float4(tf32r(wv.x), tf32r(wv.y), tf32r(wv.z), tf32r(wv.w));
        }
        __syncthreads();
        #pragma unroll
        for (int kb = 0; kb < 2; kb++) {
            uint32_t av[4];
            av[0] = __float_as_uint(As[(w*16 + g    ) * 20 + kb*8 + t    ]);
            av[1] = __float_as_uint(As[(w*16 + g + 8) * 20 + kb*8 + t    ]);
            av[2] = __float_as_uint(As[(w*16 + g    ) * 20 + kb*8 + t + 4]);
            av[3] = __float_as_uint(As[(w*16 + g + 8) * 20 + kb*8 + t + 4]);
            #pragma unroll
            for (int nt = 0; nt < 8; nt++) {
                uint32_t b0 = __float_as_uint(Ws[(nt*8 + g) * 20 + kb*8 + t    ]);
                uint32_t b1 = __float_as_uint(Ws[(nt*8 + g) * 20 + kb*8 + t + 4]);
                mma8(acc[nt], av, b0, b1);
            }
        }
    }

    const int r0 = row0 + w * 16 + g;
    #pragma unroll
    for (int nt = 0; nt < 8; nt++) {
        int cc = col0 + nt * 8 + 2 * t;
        float b0f = 0.f, b1f = 0.f;
        if (hasBias) { float2 bb = *(const float2*)&bias[cc]; b0f = bb.x; b1f = bb.y; }
        *(float2*)&C[(size_t)r0 * DIMC + cc] =
            make_float2(acc[nt][0] + b0f, acc[nt][1] + b1f);
        *(float2*)&C[(size_t)(r0 + 8) * DIMC + cc] =
            make_float2(acc[nt][2] + b0f, acc[nt][3] + b1f);
    }
}

// ---------------- tf32 tensor-core flash attention ---------------------------
// Per block: (b, h, 64-query tile). 128 threads / 4 warps; warp w owns rows
// 16w..16w+15. Q fragments held in registers for all 13 key tiles. K tile and
// P share one smem buffer; V in the other. Softmax stats live in registers
// (m16n8 C-fragment rows are spread over 4 lanes -> shfl_xor reductions).
__global__ __launch_bounds__(128) void attn_tf32(
    const float* __restrict__ qp_, const float* __restrict__ kp_,
    const float* __restrict__ vp_, float* __restrict__ ob_)
{
    __shared__ float KP[64 * 68];   // K phase: [key][d]; P phase: [m][key]
    __shared__ float Vs[64 * 68];   // [key][d]

    const int tid = threadIdx.x;
    const int w = tid >> 5, lane = tid & 31;
    const int g = lane >> 2, t = lane & 3;
    const int q0 = blockIdx.x * 64;
    const int h  = blockIdx.y;
    const int b  = blockIdx.z;

    const float* qp = qp_ + (size_t)b * T1 * DIMC + h * HD;
    const float* kp = kp_ + (size_t)b * T2 * DIMC + h * HD;
    const float* vp = vp_ + (size_t)b * T2 * DIMC + h * HD;

    // Q fragments (A-layout, m16n8k8), once for the whole block lifetime.
    uint32_t qa[8][4];
    {
        const float* p0 = qp + (size_t)(q0 + w * 16 + g) * DIMC;
        const float* p1 = p0 + 8 * DIMC;
        #pragma unroll
        for (int kb = 0; kb < 8; kb++) {
            qa[kb][0] = __float_as_uint(tf32r(p0[kb*8 + t    ]));
            qa[kb][1] = __float_as_uint(tf32r(p1[kb*8 + t    ]));
            qa[kb][2] = __float_as_uint(tf32r(p0[kb*8 + t + 4]));
            qa[kb][3] = __float_as_uint(tf32r(p1[kb*8 + t + 4]));
        }
    }

    float O[8][4] = {};
    float m0r = -INFINITY, m1r = -INFINITY, l0 = 0.f, l1 = 0.f;

    for (int kk0 = 0; kk0 < T2; kk0 += 64) {
        __syncthreads();                       // prev O-mma done with KP/Vs
        // ---- load K tile [key][d], tf32-rounded, zero-padded ----
        for (int i = tid; i < 64 * 16; i += 128) {
            int r = i >> 4, c4 = (i & 15) << 2;
            int key = kk0 + r;
            float4 v = make_float4(0.f, 0.f, 0.f, 0.f);
            if (key < T2) v = *(const float4*)(kp + (size_t)key * DIMC + c4);
            *(float4*)&KP[r * 68 + c4] =
                make_float4(tf32r(v.x), tf32r(v.y), tf32r(v.z), tf32r(v.w));
        }
        __syncthreads();

        // ---- S = Q @ K^T ----
        float S[8][4] = {};
        #pragma unroll
        for (int kb = 0; kb < 8; kb++) {
            #pragma unroll
            for (int nt = 0; nt < 8; nt++) {
                uint32_t b0 = __float_as_uint(KP[(nt*8 + g) * 68 + kb*8 + t    ]);
                uint32_t b1 = __float_as_uint(KP[(nt*8 + g) * 68 + kb*8 + t + 4]);
                mma8(S[nt], qa[kb], b0, b1);
            }
        }

        // ---- scale + mask + register online softmax ----
        float tmax0 = -INFINITY, tmax1 = -INFINITY;
        #pragma unroll
        for (int nt = 0; nt < 8; nt++) {
            int c0 = kk0 + nt * 8 + 2 * t;
            S[nt][0] = (c0     < T2) ? S[nt][0] * ATT_SCALE : -1e30f;
            S[nt][1] = (c0 + 1 < T2) ? S[nt][1] * ATT_SCALE : -1e30f;
            S[nt][2] = (c0     < T2) ? S[nt][2] * ATT_SCALE : -1e30f;
            S[nt][3] = (c0 + 1 < T2) ? S[nt][3] * ATT_SCALE : -1e30f;
            tmax0 = fmaxf(tmax0, fmaxf(S[nt][0], S[nt][1]));
            tmax1 = fmaxf(tmax1, fmaxf(S[nt][2], S[nt][3]));
        }
        tmax0 = fmaxf(tmax0, __shfl_xor_sync(0xffffffffu, tmax0, 1));
        tmax0 = fmaxf(tmax0, __shfl_xor_sync(0xffffffffu, tmax0, 2));
        tmax1 = fmaxf(tmax1, __shfl_xor_sync(0xffffffffu, tmax1, 1));
        tmax1 = fmaxf(tmax1, __shfl_xor_sync(0xffffffffu, tmax1, 2));

        float nm0 = fmaxf(m0r, tmax0), nm1 = fmaxf(m1r, tmax1);
        float cf0 = __expf(m0r - nm0), cf1 = __expf(m1r - nm1);
        m0r = nm0; m1r = nm1;

        float s0 = 0.f, s1 = 0.f;
        #pragma unroll
        for (int nt = 0; nt < 8; nt++) {
            S[nt][0] = __expf(S[nt][0] - nm0); s0 += S[nt][0];
            S[nt][1] = __expf(S[nt][1] - nm0); s0 += S[nt][1];
            S[nt][2] = __expf(S[nt][2] - nm1); s1 += S[nt][2];
            S[nt][3] = __expf(S[nt][3] - nm1); s1 += S[nt][3];
        }
        s0 += __shfl_xor_sync(0xffffffffu, s0, 1);
        s0 += __shfl_xor_sync(0xffffffffu, s0, 2);
        s1 += __shfl_xor_sync(0xffffffffu, s1, 1);
        s1 += __shfl_xor_sync(0xffffffffu, s1, 2);
        l0 = l0 * cf0 + s0;
        l1 = l1 * cf1 + s1;

        #pragma unroll
        for (int nt = 0; nt < 8; nt++) {
            O[nt][0] *= cf0; O[nt][1] *= cf0;
            O[nt][2] *= cf1; O[nt][3] *= cf1;
        }

        __syncthreads();                       // everyone done reading K
        // ---- store P (tf32) into KP as [m][key]; load V tile ----
        {
            int rp = (w * 16 + g) * 68;
            #pragma unroll
            for (int nt = 0; nt < 8; nt++) {
                *(float2*)&KP[rp + nt*8 + 2*t] =
                    make_float2(tf32r(S[nt][0]), tf32r(S[nt][1]));
                *(float2*)&KP[rp + 8*68 + nt*8 + 2*t] =
                    make_float2(tf32r(S[nt][2]), tf32r(S[nt][3]));
            }
        }
        for (int i = tid; i < 64 * 16; i += 128) {
            int r = i >> 4, c4 = (i & 15) << 2;
            int key = kk0 + r;
            float4 v = make_float4(0.f, 0.f, 0.f, 0.f);
            if (key < T2) v = *(const float4*)(vp + (size_t)key * DIMC + c4);
            *(float4*)&Vs[r * 68 + c4] =
                make_float4(tf32r(v.x), tf32r(v.y), tf32r(v.z), tf32r(v.w));
        }
        __syncthreads();

        // ---- O += P @ V ----
        #pragma unroll
        for (int kb = 0; kb < 8; kb++) {
            uint32_t pa[4];
            int rp = (w * 16 + g) * 68;
            pa[0] = __float_as_uint(KP[rp +        kb*8 + t    ]);
            pa[1] = __float_as_uint(KP[rp + 8*68 + kb*8 + t    ]);
            pa[2] = __float_as_uint(KP[rp +        kb*8 + t + 4]);
            pa[3] = __float_as_uint(KP[rp + 8*68 + kb*8 + t + 4]);
            #pragma unroll
            for (int nt = 0; nt < 8; nt++) {
                uint32_t b0 = __float_as_uint(Vs[(kb*8 + t    ) * 68 + nt*8 + g]);
                uint32_t b1 = __float_as_uint(Vs[(kb*8 + t + 4) * 68 + nt*8 + g]);
                mma8(O[nt], pa, b0, b1);
            }
        }
    }

    // ---- finalize ----
    float inv0 = 1.f / l0, inv1 = 1.f / l1;
    float* obp = ob_ + ((size_t)b * T1 + q0 + w * 16 + g) * DIMC + h * HD;
    #pragma unroll
    for (int nt = 0; nt < 8; nt++) {
        *(float2*)&obp[nt*8 + 2*t] =
            make_float2(O[nt][0] * inv0, O[nt][1] * inv0);
        *(float2*)&obp[(size_t)8 * DIMC + nt*8 + 2*t] =
            make_float2(O[nt][2] * inv1, O[nt][3] * inv1);
    }
}

// ---------------- launch -----------------------------------------------------
extern "C" void kernel_launch(void* const* d_in, const int* in_sizes, int n_in,
                              void* d_out, int out_size)
{
    (void)in_sizes; (void)n_in; (void)out_size;
    const float* x      = (const float*)d_in[0];
    const float* conv_q = (const float*)d_in[3];
    const float* bnq_s  = (const float*)d_in[4];
    const float* bnq_b  = (const float*)d_in[5];
    const float* bnq_m  = (const float*)d_in[6];
    const float* bnq_v  = (const float*)d_in[7];
    const float* conv_k = (const float*)d_in[8];
    const float* bnk_s  = (const float*)d_in[9];
    const float* bnk_b  = (const float*)d_in[10];
    const float* bnk_m  = (const float*)d_in[11];
    const float* bnk_v  = (const float*)d_in[12];
    const float* conv_v = (const float*)d_in[13];
    const float* bnv_s  = (const float*)d_in[14];
    const float* bnv_b  = (const float*)d_in[15];
    const float* bnv_m  = (const float*)d_in[16];
    const float* bnv_v  = (const float*)d_in[17];
    const float* wq     = (const float*)d_in[18];
    const float* wk     = (const float*)d_in[19];
    const float* wv     = (const float*)d_in[20];
    const float* w_last = (const float*)d_in[21];
    const float* b_last = (const float*)d_in[22];
    float* out = (float*)d_out;

    float *qf, *kf, *vf, *qp, *kp, *vp, *ob;
    cudaGetSymbolAddress((void**)&qf, g_qf);
    cudaGetSymbolAddress((void**)&kf, g_kf);
    cudaGetSymbolAddress((void**)&vf, g_vf);
    cudaGetSymbolAddress((void**)&qp, g_qp);
    cudaGetSymbolAddress((void**)&kp, g_kp);
    cudaGetSymbolAddress((void**)&vp, g_vp);
    cudaGetSymbolAddress((void**)&ob, g_ob);

    dwconv_s1<<<B_ * T1, DIMC>>>(x, conv_q, bnq_s, bnq_b, bnq_m, bnq_v, qf);
    dwconv_s2<<<B_ * T2, DIMC>>>(x, conv_k, bnk_s, bnk_b, bnk_m, bnk_v,
                                    conv_v, bnv_s, bnv_b, bnv_m, bnv_v, kf, vf);

    dim3 gbig(DIMC / 64, (B_ * T1) / 64);   // (6, 392)
    dim3 gsml(DIMC / 64, (B_ * T2) / 64);   // (6, 98)
    gemm_tf32<<<gbig, 128>>>(qf, wq, nullptr, qp, 0);
    gemm_tf32<<<gsml, 128>>>(kf, wk, nullptr, kp, 0);
    gemm_tf32<<<gsml, 128>>>(vf, wv, nullptr, vp, 0);

    dim3 gattn(T1 / 64, NHEADS, B_);        // (49, 6, 8)
    attn_tf32<<<gattn, 128>>>(qp, kp, vp, ob);

    gemm_tf32<<<gbig, 128>>>(ob, w_last, b_last, out, 1);
}

// round 5
// speedup vs baseline: 3.1628x; 1.0805x over previous
#include <cuda_runtime.h>
#include <math.h>
#include <stdint.h>

#define DIMC 384
#define B_   8
#define HH   56
#define WW   56
#define T1   3136
#define H2   28
#define W2   28
#define T2   784
#define NHEADS 6
#define HD   64
#define EPSBN 1e-5f
#define ATT_SCALE 0.05103103630798288f   /* 384^-0.5 (full dim, per reference) */
#define LOG2E 1.4426950408889634f

// ---------------- scratch ---------------------------------------------------
__device__ float g_qf[B_ * T1 * DIMC];
__device__ float g_kf[B_ * T2 * DIMC];
__device__ float g_vf[B_ * T2 * DIMC];
__device__ float g_qp[B_ * T1 * DIMC];
__device__ float g_kp[B_ * T2 * DIMC];
__device__ float g_vp[B_ * T2 * DIMC];
__device__ float g_ob[B_ * T1 * DIMC];

// ---------------- helpers ---------------------------------------------------
__device__ __forceinline__ float tf32r(float x) {
    uint32_t u;
    asm("cvt.rna.tf32.f32 %0, %1;" : "=r"(u) : "f"(x));
    return __uint_as_float(u);
}

__device__ __forceinline__ void mma8(float* d, const uint32_t* a, uint32_t b0, uint32_t b1) {
    asm volatile(
        "mma.sync.aligned.m16n8k8.row.col.f32.tf32.tf32.f32 "
        "{%0,%1,%2,%3}, {%4,%5,%6,%7}, {%8,%9}, {%0,%1,%2,%3};\n"
        : "+f"(d[0]), "+f"(d[1]), "+f"(d[2]), "+f"(d[3])
        : "r"(a[0]), "r"(a[1]), "r"(a[2]), "r"(a[3]), "r"(b0), "r"(b1));
}

// ---------------- depthwise conv 3x3 stride 1 + BN (row-sliding) -------------
// One block per (b, y); thread = channel; slide a 3x3 window along x.
__global__ __launch_bounds__(DIMC) void dwconv_s1(
    const float* __restrict__ x, const float* __restrict__ cw,
    const float* __restrict__ gs, const float* __restrict__ gb,
    const float* __restrict__ gm, const float* __restrict__ gv,
    float* __restrict__ out)
{
    const int by = blockIdx.x;
    const int b  = by / HH, y = by % HH;
    const int c  = threadIdx.x;

    const float w0 = cw[c*9+0], w1 = cw[c*9+1], w2 = cw[c*9+2];
    const float w3 = cw[c*9+3], w4 = cw[c*9+4], w5 = cw[c*9+5];
    const float w6 = cw[c*9+6], w7 = cw[c*9+7], w8 = cw[c*9+8];
    const float inv = rsqrtf(gv[c] + EPSBN);
    const float sc  = gs[c] * inv;
    const float bb  = gb[c] - gm[c] * sc;

    const float* base = x + (size_t)b * T1 * DIMC + c;
    const bool v0 = (y > 0), v2 = (y < HH - 1);
    const float* r0 = base + (size_t)(y - 1) * WW * DIMC;
    const float* r1 = base + (size_t)y * WW * DIMC;
    const float* r2 = base + (size_t)(y + 1) * WW * DIMC;
    float* op = out + ((size_t)b * T1 + (size_t)y * WW) * DIMC + c;

    float a0 = 0.f, a1 = 0.f, a2 = 0.f;                     // col x-1
    float b0 = v0 ? r0[0] : 0.f;                            // col x
    float b1 = r1[0];
    float b2 = v2 ? r2[0] : 0.f;
    float c0 = v0 ? r0[DIMC] : 0.f;                         // col x+1
    float c1 = r1[DIMC];
    float c2 = v2 ? r2[DIMC] : 0.f;

    #pragma unroll 4
    for (int xw = 0; xw < WW; xw++) {
        float acc = a0*w0 + b0*w1 + c0*w2
                  + a1*w3 + b1*w4 + c1*w5
                  + a2*w6 + b2*w7 + c2*w8;
        op[(size_t)xw * DIMC] = acc * sc + bb;
        a0 = b0; a1 = b1; a2 = b2;
        b0 = c0; b1 = c1; b2 = c2;
        if (xw + 2 < WW) {
            size_t off = (size_t)(xw + 2) * DIMC;
            c0 = v0 ? r0[off] : 0.f;
            c1 = r1[off];
            c2 = v2 ? r2[off] : 0.f;
        } else { c0 = c1 = c2 = 0.f; }
    }
}

// ---------------- depthwise conv 3x3 stride 2 + BN (k and v fused) -----------
__global__ __launch_bounds__(DIMC) void dwconv_s2(
    const float* __restrict__ x,
    const float* __restrict__ cwk, const float* __restrict__ ksc, const float* __restrict__ kbi,
    const float* __restrict__ kmu, const float* __restrict__ kva,
    const float* __restrict__ cwv, const float* __restrict__ vsc, const float* __restrict__ vbi,
    const float* __restrict__ vmu, const float* __restrict__ vva,
    float* __restrict__ outk, float* __restrict__ outv)
{
    const int by = blockIdx.x;
    const int b  = by / H2, oy = by % H2;
    const int c  = threadIdx.x;
    const int y  = 2 * oy;

    float wk[9], wv[9];
    #pragma unroll
    for (int i = 0; i < 9; i++) { wk[i] = cwk[c*9+i]; wv[i] = cwv[c*9+i]; }
    const float invk = rsqrtf(kva[c] + EPSBN);
    const float sck  = ksc[c] * invk;
    const float bbk  = kbi[c] - kmu[c] * sck;
    const float invv = rsqrtf(vva[c] + EPSBN);
    const float scv  = vsc[c] * invv;
    const float bbv  = vbi[c] - vmu[c] * scv;

    const float* base = x + (size_t)b * T1 * DIMC + c;
    const bool v0 = (y > 0), v2 = (y < HH - 1);
    const float* r0 = base + (size_t)(y - 1) * WW * DIMC;
    const float* r1 = base + (size_t)y * WW * DIMC;
    const float* r2 = base + (size_t)(y + 1) * WW * DIMC;
    float* opk = outk + ((size_t)b * T2 + (size_t)oy * W2) * DIMC + c;
    float* opv = outv + ((size_t)b * T2 + (size_t)oy * W2) * DIMC + c;

    // window cols: a = 2ox-1, b = 2ox, c = 2ox+1
    float a0 = 0.f, a1 = 0.f, a2 = 0.f;
    float b0 = v0 ? r0[0] : 0.f, b1 = r1[0], b2 = v2 ? r2[0] : 0.f;
    float c0 = v0 ? r0[DIMC] : 0.f, c1 = r1[DIMC], c2 = v2 ? r2[DIMC] : 0.f;

    #pragma unroll 2
    for (int ox = 0; ox < W2; ox++) {
        float ak = a0*wk[0] + b0*wk[1] + c0*wk[2]
                 + a1*wk[3] + b1*wk[4] + c1*wk[5]
                 + a2*wk[6] + b2*wk[7] + c2*wk[8];
        float av = a0*wv[0] + b0*wv[1] + c0*wv[2]
                 + a1*wv[3] + b1*wv[4] + c1*wv[5]
                 + a2*wv[6] + b2*wv[7] + c2*wv[8];
        opk[(size_t)ox * DIMC] = ak * sck + bbk;
        opv[(size_t)ox * DIMC] = av * scv + bbv;
        if (ox + 1 < W2) {
            size_t o1 = (size_t)(2*ox + 2) * DIMC;
            size_t o2 = (size_t)(2*ox + 3) * DIMC;
            a0 = c0; a1 = c1; a2 = c2;
            b0 = v0 ? r0[o1] : 0.f; b1 = r1[o1]; b2 = v2 ? r2[o1] : 0.f;
            c0 = v0 ? r0[o2] : 0.f; c1 = r1[o2]; c2 = v2 ? r2[o2] : 0.f;
        }
    }
}

// ---------------- tf32 tensor-core GEMM: C = A[M,384] @ W[384,384]^T (+bias) --
// 128x64 tile, 256 threads (8 warps), double-buffered smem, 1 sync / k-step.
__global__ __launch_bounds__(256, 3) void gemm_tf32(
    const float* __restrict__ A, const float* __restrict__ W,
    const float* __restrict__ bias, float* __restrict__ C, int hasBias)
{
    __shared__ float As[2][128 * 20];
    __shared__ float Ws[2][64 * 20];

    const int tid = threadIdx.x;
    const int w = tid >> 5, lane = tid & 31;
    const int g = lane >> 2, t = lane & 3;
    const int row0 = blockIdx.y * 128, col0 = blockIdx.x * 64;

    const int ra = tid >> 2;                 // Ws row / As row base
    const int ca = (tid & 3) << 2;

    float acc[8][4] = {};

    // prime buffer 0
    {
        #pragma unroll
        for (int p = 0; p < 2; p++) {
            int r = ra + p * 64;
            float4 a = *(const float4*)(A + (size_t)(row0 + r) * DIMC + ca);
            *(float4*)&As[0][r * 20 + ca] =
                make_float4(tf32r(a.x), tf32r(a.y), tf32r(a.z), tf32r(a.w));
        }
        float4 wv = *(const float4*)(W + (size_t)(col0 + ra) * DIMC + ca);
        *(float4*)&Ws[0][ra * 20 + ca] =
            make_float4(tf32r(wv.x), tf32r(wv.y), tf32r(wv.z), tf32r(wv.w));
    }
    __syncthreads();

    for (int ks = 0; ks < 24; ks++) {
        const int cur = ks & 1;
        const bool more = (ks < 23);
        float4 pa0, pa1, pw0;
        if (more) {
            int k0 = (ks + 1) * 16;
            pa0 = *(const float4*)(A + (size_t)(row0 + ra) * DIMC + k0 + ca);
            pa1 = *(const float4*)(A + (size_t)(row0 + ra + 64) * DIMC + k0 + ca);
            pw0 = *(const float4*)(W + (size_t)(col0 + ra) * DIMC + k0 + ca);
        }

        const float* Ac = As[cur];
        const float* Wc = Ws[cur];
        #pragma unroll
        for (int kb = 0; kb < 2; kb++) {
            uint32_t av[4];
            av[0] = __float_as_uint(Ac[(w*16 + g    ) * 20 + kb*8 + t    ]);
            av[1] = __float_as_uint(Ac[(w*16 + g + 8) * 20 + kb*8 + t    ]);
            av[2] = __float_as_uint(Ac[(w*16 + g    ) * 20 + kb*8 + t + 4]);
            av[3] = __float_as_uint(Ac[(w*16 + g + 8) * 20 + kb*8 + t + 4]);
            #pragma unroll
            for (int nt = 0; nt < 8; nt++) {
                uint32_t b0 = __float_as_uint(Wc[(nt*8 + g) * 20 + kb*8 + t    ]);
                uint32_t b1 = __float_as_uint(Wc[(nt*8 + g) * 20 + kb*8 + t + 4]);
                mma8(acc[nt], av, b0, b1);
            }
        }

        if (more) {
            const int nxt = cur ^ 1;
            *(float4*)&As[nxt][ra * 20 + ca] =
                make_float4(tf32r(pa0.x), tf32r(pa0.y), tf32r(pa0.z), tf32r(pa0.w));
            *(float4*)&As[nxt][(ra + 64) * 20 + ca] =
                make_float4(tf32r(pa1.x), tf32r(pa1.y), tf32r(pa1.z), tf32r(pa1.w));
            *(float4*)&Ws[nxt][ra * 20 + ca] =
                make_float4(tf32r(pw0.x), tf32r(pw0.y), tf32r(pw0.z), tf32r(pw0.w));
        }
        __syncthreads();
    }

    const int r0 = row0 + w * 16 + g;
    #pragma unroll
    for (int nt = 0; nt < 8; nt++) {
        int cc = col0 + nt * 8 + 2 * t;
        float b0f = 0.f, b1f = 0.f;
        if (hasBias) { float2 bb = *(const float2*)&bias[cc]; b0f = bb.x; b1f = bb.y; }
        *(float2*)&C[(size_t)r0 * DIMC + cc] =
            make_float2(acc[nt][0] + b0f, acc[nt][1] + b1f);
        *(float2*)&C[(size_t)(r0 + 8) * DIMC + cc] =
            make_float2(acc[nt][2] + b0f, acc[nt][3] + b1f);
    }
}

// ---------------- tf32 tensor-core flash attention ---------------------------
// Per block: (b, h, 128-query tile). 256 threads / 8 warps; warp w owns rows
// 16w..16w+15. P never touches smem: the S C-fragment is permuted into the
// P.V A-fragment with shuffles. exp2-domain softmax; scale folded into Q.
__global__ __launch_bounds__(256, 2) void attn_tf32(
    const float* __restrict__ qp_, const float* __restrict__ kp_,
    const float* __restrict__ vp_, float* __restrict__ ob_)
{
    __shared__ float Ks[64 * 68];
    __shared__ float Vs[64 * 68];

    const int tid = threadIdx.x;
    const int w = tid >> 5, lane = tid & 31;
    const int g = lane >> 2, t = lane & 3;
    const int q0 = blockIdx.x * 128;
    const int h  = blockIdx.y;
    const int b  = blockIdx.z;

    const float* qp = qp_ + (size_t)b * T1 * DIMC + h * HD;
    const float* kp = kp_ + (size_t)b * T2 * DIMC + h * HD;
    const float* vp = vp_ + (size_t)b * T2 * DIMC + h * HD;

    const int qrow = q0 + w * 16 + g;               // this thread's row pair base
    const bool qvalid = (qrow + 8) < T1 || qrow < T1; // rows qrow, qrow+8
    const int qr0 = qrow < T1 ? qrow : T1 - 1;
    const int qr1 = (qrow + 8) < T1 ? qrow + 8 : T1 - 1;

    // Q fragments with ATT_SCALE*log2(e) folded in.
    const float qmul = ATT_SCALE * LOG2E;
    uint32_t qa[8][4];
    {
        const float* p0 = qp + (size_t)qr0 * DIMC;
        const float* p1 = qp + (size_t)qr1 * DIMC;
        #pragma unroll
        for (int kb = 0; kb < 8; kb++) {
            qa[kb][0] = __float_as_uint(tf32r(p0[kb*8 + t    ] * qmul));
            qa[kb][1] = __float_as_uint(tf32r(p1[kb*8 + t    ] * qmul));
            qa[kb][2] = __float_as_uint(tf32r(p0[kb*8 + t + 4] * qmul));
            qa[kb][3] = __float_as_uint(tf32r(p1[kb*8 + t + 4] * qmul));
        }
    }

    float O[8][4] = {};
    float m0r = -INFINITY, m1r = -INFINITY, l0 = 0.f, l1 = 0.f;

    for (int kk0 = 0; kk0 < T2; kk0 += 64) {
        __syncthreads();                       // prev tile done with Ks/Vs
        // ---- load K tile [key][d] (tf32), zero-padded ----
        for (int i = tid; i < 64 * 16; i += 256) {
            int r = i >> 4, c4 = (i & 15) << 2;
            int key = kk0 + r;
            float4 v = make_float4(0.f, 0.f, 0.f, 0.f);
            if (key < T2) v = *(const float4*)(kp + (size_t)key * DIMC + c4);
            *(float4*)&Ks[r * 68 + c4] =
                make_float4(tf32r(v.x), tf32r(v.y), tf32r(v.z), tf32r(v.w));
        }
        __syncthreads();

        // ---- S = Q @ K^T (already in exp2 domain scale) ----
        float S[8][4] = {};
        #pragma unroll
        for (int kb = 0; kb < 8; kb++) {
            #pragma unroll
            for (int nt = 0; nt < 8; nt++) {
                uint32_t b0 = __float_as_uint(Ks[(nt*8 + g) * 68 + kb*8 + t    ]);
                uint32_t b1 = __float_as_uint(Ks[(nt*8 + g) * 68 + kb*8 + t + 4]);
                mma8(S[nt], qa[kb], b0, b1);
            }
        }

        // ---- mask + online softmax (exp2 domain, all in registers) ----
        float tmax0 = -INFINITY, tmax1 = -INFINITY;
        #pragma unroll
        for (int nt = 0; nt < 8; nt++) {
            int c0 = kk0 + nt * 8 + 2 * t;
            if (c0 >= T2)     { S[nt][0] = -1e30f; S[nt][2] = -1e30f; }
            if (c0 + 1 >= T2) { S[nt][1] = -1e30f; S[nt][3] = -1e30f; }
            tmax0 = fmaxf(tmax0, fmaxf(S[nt][0], S[nt][1]));
            tmax1 = fmaxf(tmax1, fmaxf(S[nt][2], S[nt][3]));
        }
        tmax0 = fmaxf(tmax0, __shfl_xor_sync(0xffffffffu, tmax0, 1));
        tmax0 = fmaxf(tmax0, __shfl_xor_sync(0xffffffffu, tmax0, 2));
        tmax1 = fmaxf(tmax1, __shfl_xor_sync(0xffffffffu, tmax1, 1));
        tmax1 = fmaxf(tmax1, __shfl_xor_sync(0xffffffffu, tmax1, 2));

        float nm0 = fmaxf(m0r, tmax0), nm1 = fmaxf(m1r, tmax1);
        float cf0 = exp2f(m0r - nm0), cf1 = exp2f(m1r - nm1);
        m0r = nm0; m1r = nm1;

        float s0 = 0.f, s1 = 0.f;
        #pragma unroll
        for (int nt = 0; nt < 8; nt++) {
            S[nt][0] = exp2f(S[nt][0] - nm0); s0 += S[nt][0];
            S[nt][1] = exp2f(S[nt][1] - nm0); s0 += S[nt][1];
            S[nt][2] = exp2f(S[nt][2] - nm1); s1 += S[nt][2];
            S[nt][3] = exp2f(S[nt][3] - nm1); s1 += S[nt][3];
        }
        s0 += __shfl_xor_sync(0xffffffffu, s0, 1);
        s0 += __shfl_xor_sync(0xffffffffu, s0, 2);
        s1 += __shfl_xor_sync(0xffffffffu, s1, 1);
        s1 += __shfl_xor_sync(0xffffffffu, s1, 2);
        l0 = l0 * cf0 + s0;
        l1 = l1 * cf1 + s1;

        #pragma unroll
        for (int nt = 0; nt < 8; nt++) {
            O[nt][0] *= cf0; O[nt][1] *= cf0;
            O[nt][2] *= cf1; O[nt][3] *= cf1;
        }

        // ---- load V tile [key][d] (tf32) into Vs ----
        for (int i = tid; i < 64 * 16; i += 256) {
            int r = i >> 4, c4 = (i & 15) << 2;
            int key = kk0 + r;
            float4 v = make_float4(0.f, 0.f, 0.f, 0.f);
            if (key < T2) v = *(const float4*)(vp + (size_t)key * DIMC + c4);
            *(float4*)&Vs[r * 68 + c4] =
                make_float4(tf32r(v.x), tf32r(v.y), tf32r(v.z), tf32r(v.w));
        }
        __syncthreads();

        // ---- O += P @ V : P A-fragments built from S via shuffles ----
        const int L0 = (lane & 28) | (t >> 1);
        const int L2 = L0 + 2;
        const bool odd = (t & 1);
        #pragma unroll
        for (int kb = 0; kb < 8; kb++) {
            float e0 = __shfl_sync(0xffffffffu, S[kb][0], L0);
            float e1 = __shfl_sync(0xffffffffu, S[kb][1], L0);
            float f0 = __shfl_sync(0xffffffffu, S[kb][2], L0);
            float f1 = __shfl_sync(0xffffffffu, S[kb][3], L0);
            float h0 = __shfl_sync(0xffffffffu, S[kb][0], L2);
            float h1 = __shfl_sync(0xffffffffu, S[kb][1], L2);
            float i0 = __shfl_sync(0xffffffffu, S[kb][2], L2);
            float i1 = __shfl_sync(0xffffffffu, S[kb][3], L2);
            uint32_t pa[4];
            pa[0] = __float_as_uint(odd ? e1 : e0);
            pa[1] = __float_as_uint(odd ? f1 : f0);
            pa[2] = __float_as_uint(odd ? h1 : h0);
            pa[3] = __float_as_uint(odd ? i1 : i0);
            #pragma unroll
            for (int nt = 0; nt < 8; nt++) {
                uint32_t b0 = __float_as_uint(Vs[(kb*8 + t    ) * 68 + nt*8 + g]);
                uint32_t b1 = __float_as_uint(Vs[(kb*8 + t + 4) * 68 + nt*8 + g]);
                mma8(O[nt], pa, b0, b1);
            }
        }
    }

    // ---- finalize ----
    float inv0 = 1.f / l0, inv1 = 1.f / l1;
    if (qrow < T1) {
        float* o0 = ob_ + ((size_t)b * T1 + qrow) * DIMC + h * HD;
        #pragma unroll
        for (int nt = 0; nt < 8; nt++)
            *(float2*)&o0[nt*8 + 2*t] = make_float2(O[nt][0] * inv0, O[nt][1] * inv0);
    }
    if (qrow + 8 < T1) {
        float* o1 = ob_ + ((size_t)b * T1 + qrow + 8) * DIMC + h * HD;
        #pragma unroll
        for (int nt = 0; nt < 8; nt++)
            *(float2*)&o1[nt*8 + 2*t] = make_float2(O[nt][2] * inv1, O[nt][3] * inv1);
    }
    (void)qvalid;
}

// ---------------- launch -----------------------------------------------------
extern "C" void kernel_launch(void* const* d_in, const int* in_sizes, int n_in,
                              void* d_out, int out_size)
{
    (void)in_sizes; (void)n_in; (void)out_size;
    const float* x      = (const float*)d_in[0];
    const float* conv_q = (const float*)d_in[3];
    const float* bnq_s  = (const float*)d_in[4];
    const float* bnq_b  = (const float*)d_in[5];
    const float* bnq_m  = (const float*)d_in[6];
    const float* bnq_v  = (const float*)d_in[7];
    const float* conv_k = (const float*)d_in[8];
    const float* bnk_s  = (const float*)d_in[9];
    const float* bnk_b  = (const float*)d_in[10];
    const float* bnk_m  = (const float*)d_in[11];
    const float* bnk_v  = (const float*)d_in[12];
    const float* conv_v = (const float*)d_in[13];
    const float* bnv_s  = (const float*)d_in[14];
    const float* bnv_b  = (const float*)d_in[15];
    const float* bnv_m  = (const float*)d_in[16];
    const float* bnv_v  = (const float*)d_in[17];
    const float* wq     = (const float*)d_in[18];
    const float* wk     = (const float*)d_in[19];
    const float* wv     = (const float*)d_in[20];
    const float* w_last = (const float*)d_in[21];
    const float* b_last = (const float*)d_in[22];
    float* out = (float*)d_out;

    float *qf, *kf, *vf, *qp, *kp, *vp, *ob;
    cudaGetSymbolAddress((void**)&qf, g_qf);
    cudaGetSymbolAddress((void**)&kf, g_kf);
    cudaGetSymbolAddress((void**)&vf, g_vf);
    cudaGetSymbolAddress((void**)&qp, g_qp);
    cudaGetSymbolAddress((void**)&kp, g_kp);
    cudaGetSymbolAddress((void**)&vp, g_vp);
    cudaGetSymbolAddress((void**)&ob, g_ob);

    dwconv_s1<<<B_ * HH, DIMC>>>(x, conv_q, bnq_s, bnq_b, bnq_m, bnq_v, qf);
    dwconv_s2<<<B_ * H2, DIMC>>>(x, conv_k, bnk_s, bnk_b, bnk_m, bnk_v,
                                    conv_v, bnv_s, bnv_b, bnv_m, bnv_v, kf, vf);

    dim3 gbig(DIMC / 64, (B_ * T1) / 128);   // (6, 196)
    dim3 gsml(DIMC / 64, (B_ * T2) / 128);   // (6, 49)
    gemm_tf32<<<gbig, 256>>>(qf, wq, nullptr, qp, 0);
    gemm_tf32<<<gsml, 256>>>(kf, wk, nullptr, kp, 0);
    gemm_tf32<<<gsml, 256>>>(vf, wv, nullptr, vp, 0);

    dim3 gattn((T1 + 127) / 128, NHEADS, B_);  // (25, 6, 8)
    attn_tf32<<<gattn, 256>>>(qp, kp, vp, ob);

    gemm_tf32<<<gbig, 256>>>(ob, w_last, b_last, out, 1);
}